// round 17
// baseline (speedup 1.0000x reference)
#include <cuda_runtime.h>
#include <cuda_fp16.h>
#include <math.h>
#include <stdint.h>

#define FULLMASK 0xffffffffu

constexpr int NAG  = 8;
constexpr int B    = 16384;
constexpr int SD   = 64;
constexpr int AD   = 16;
constexpr int KSA  = 80;
constexpr int HID  = 128;
constexpr int HEADS= 4;
constexpr int D    = 32;
constexpr float EPS = 1e-5f;

// -------- scratch --------
__device__ __align__(16) float g_part [NAG * 16 * KSA];
__device__ __align__(16) float g_partq[NAG * 16 * KSA];
__device__ __align__(16) __half g_se [(size_t)NAG * B * HID];   // fp16 FRAGMENT-ORDER 64-row tiles
__device__ __align__(16) __half g_key[(size_t)NAG * B * HID];   // fp16 row-major
__device__ __align__(16) __half g_val[(size_t)NAG * B * HID];
__device__ __align__(16) __half g_sel[(size_t)NAG * B * HID];
__device__ __align__(16) __half g_oth[(size_t)NAG * B * HID];   // fp16 row-major

// fragment-order fp16 weights
__device__ __align__(16) uint2 pWsa16[NAG][16 * 5 * 32];   // [(n8*5+ksh)*32+lane]
__device__ __align__(16) uint2 pWse16[NAG][16 * 4 * 32];   // [(n8*4+ksh)*32+lane]
__device__ __align__(16) uint2 pWk16 [8 * 16 * 32];        // [(n8*8+ksh)*32+lane]
__device__ __align__(16) uint2 pWv16 [8 * 16 * 32];
__device__ __align__(16) uint2 pWsel16[8 * 16 * 32];
__device__ __align__(16) uint2 pWc116[NAG][16 * 16 * 32];  // [(n8*16+ksh)*32+lane]

__device__ __forceinline__ float lrelu(float x) { return x > 0.f ? x : 0.01f * x; }

// pack (lo,hi) floats -> f16x2 (lo in low half)
__device__ __forceinline__ uint32_t h2(float lo, float hi) {
    uint32_t r; asm("cvt.rn.f16x2.f32 %0, %1, %2;" : "=r"(r) : "f"(hi), "f"(lo)); return r;
}
__device__ __forceinline__ void mma16(float4& d, const uint4 a, const uint2 b) {
    asm volatile(
        "mma.sync.aligned.m16n8k16.row.col.f32.f16.f16.f32 "
        "{%0,%1,%2,%3}, {%4,%5,%6,%7}, {%8,%9}, {%0,%1,%2,%3};"
        : "+f"(d.x), "+f"(d.y), "+f"(d.z), "+f"(d.w)
        : "r"(a.x), "r"(a.y), "r"(a.z), "r"(a.w), "r"(b.x), "r"(b.y));
}
__device__ __forceinline__ void cp16(void* smem_dst, const void* gsrc) {
    uint32_t sa = (uint32_t)__cvta_generic_to_shared(smem_dst);
    asm volatile("cp.async.cg.shared.global [%0], [%1], 16;" :: "r"(sa), "l"(gsrc));
}
#define CP_COMMIT()  asm volatile("cp.async.commit_group;")
#define CP_WAITG(n)  asm volatile("cp.async.wait_group " #n ";" ::: "memory")

// fp16 fragment-order A load (8-ksh tile): one LDS.128
__device__ __forceinline__ uint4 ldfrag16(const uint32_t* A16, int g16, int ksh, int lane) {
    return *(const uint4*)(A16 + (((g16 << 3) + ksh) << 7) + (lane << 2));
}
// store one (mi,j) accumulator's 4 values as fp16 fragment words (8-ksh tile)
__device__ __forceinline__ void st_frag16(uint32_t* A16, int g16, int n8, int tig, int g, float4 v) {
    int C = n8 * 8 + 2 * tig;
    int ksh = C >> 4;
    int co  = C & 15;
    int rego = (co >= 8) ? 2 : 0;
    int lanep = g * 4 + ((co & 7) >> 1);
    uint32_t* base = A16 + ((((g16 << 3) + ksh) << 5) + lanep) * 4;
    base[rego]     = h2(v.x, v.y);   // row R  : cols C,C+1
    base[rego + 1] = h2(v.z, v.w);   // row R+8
}

// ============================================================
// K0: prep (fp16 weight fragments) + BN partial stats, fused
// ============================================================
__global__ void __launch_bounds__(512)
k_prep_stats(const float* __restrict__ Wk, const float* __restrict__ Wv,
             const float* __restrict__ Wsel, const float* __restrict__ Wsa,
             const float* __restrict__ Wse, const float* __restrict__ Wc1,
             const float* __restrict__ s, const float* __restrict__ a)
{
    __shared__ float r1[512], r2[512];
    const int tid = threadIdx.x;

    if (blockIdx.x < 224) {
        int i = blockIdx.x * 512 + tid;
        if (i < 12288) {
            int which = i >> 12;
            int j = i & 4095;
            int n8 = j >> 8, ksh = (j >> 5) & 7, lane = j & 31;
            int g = lane >> 2, tig = lane & 3;
            int n = n8 * 8 + g, k0 = ksh * 16 + tig * 2;
            const float* W = which == 0 ? Wk : (which == 1 ? Wv : Wsel);
            const float* base = W + (n >> 5) * (HID * D) + (n & 31);
            uint2 v = make_uint2(h2(base[k0 * 32],       base[(k0 + 1) * 32]),
                                 h2(base[(k0 + 8) * 32], base[(k0 + 9) * 32]));
            (which == 0 ? pWk16 : which == 1 ? pWv16 : pWsel16)[j] = v;
            return;
        }
        int i2 = i - 12288;
        if (i2 < NAG * 2560) {
            int n = i2 / 2560, j = i2 % 2560;
            int n8 = j / 160, rem = j % 160;
            int ksh = rem >> 5, lane = rem & 31;
            int g = lane >> 2, tig = lane & 3;
            int nn = n8 * 8 + g, k0 = ksh * 16 + tig * 2;
            const float* W = Wsa + n * KSA * HID;
            pWsa16[n][j] = make_uint2(h2(W[k0 * HID + nn],       W[(k0 + 1) * HID + nn]),
                                      h2(W[(k0 + 8) * HID + nn], W[(k0 + 9) * HID + nn]));
            return;
        }
        int i3 = i2 - NAG * 2560;
        if (i3 < NAG * 2048) {
            int n = i3 >> 11, j = i3 & 2047;
            int n8 = j >> 7, ksh = (j >> 5) & 3, lane = j & 31;
            int g = lane >> 2, tig = lane & 3;
            int nn = n8 * 8 + g, k0 = ksh * 16 + tig * 2;
            const float* W = Wse + n * SD * HID;
            pWse16[n][j] = make_uint2(h2(W[k0 * HID + nn],       W[(k0 + 1) * HID + nn]),
                                      h2(W[(k0 + 8) * HID + nn], W[(k0 + 9) * HID + nn]));
            return;
        }
        int i4 = i3 - NAG * 2048;
        if (i4 < NAG * 8192) {
            int n = i4 >> 13, j = i4 & 8191;
            int lane = j & 31, ksh = (j >> 5) & 15, n8 = j >> 9;
            int g = lane >> 2, tig = lane & 3;
            int nn = n8 * 8 + g, k0 = ksh * 16 + tig * 2;
            const float* W = Wc1 + (size_t)n * 2 * HID * HID;
            pWc116[n][j] = make_uint2(h2(W[k0 * 128 + nn],       W[(k0 + 1) * 128 + nn]),
                                      h2(W[(k0 + 8) * 128 + nn], W[(k0 + 9) * 128 + nn]));
        }
        return;
    }

    const int bx = blockIdx.x - 224;
    const int n = bx >> 4, chunk = bx & 15;
    const size_t row0 = (size_t)n * B + chunk * 1024;
    float* part  = g_part  + (n * 16 + chunk) * KSA;
    float* partq = g_partq + (n * 16 + chunk) * KSA;

    {
        const int f = tid & 63, r0 = tid >> 6;
        float sum = 0.f, sq = 0.f;
        const float* p = s + (row0 + r0) * SD + f;
        #pragma unroll 4
        for (int st = 0; st < 128; st++) {
            float x = p[(size_t)st * 8 * SD];
            sum += x; sq += x * x;
        }
        r1[tid] = sum; r2[tid] = sq;
        __syncthreads();
        #pragma unroll
        for (int o = 4; o > 0; o >>= 1) {
            if (tid < o * 64) { r1[tid] += r1[tid + o * 64]; r2[tid] += r2[tid + o * 64]; }
            __syncthreads();
        }
        if (tid < 64) { part[tid] = r1[tid]; partq[tid] = r2[tid]; }
        __syncthreads();
    }
    {
        const int f = tid & 15, r0 = tid >> 4;
        float sum = 0.f, sq = 0.f;
        const float* p = a + (row0 + r0) * AD + f;
        #pragma unroll 4
        for (int st = 0; st < 32; st++) {
            float x = p[(size_t)st * 32 * AD];
            sum += x; sq += x * x;
        }
        r1[tid] = sum; r2[tid] = sq;
        __syncthreads();
        #pragma unroll
        for (int o = 16; o > 0; o >>= 1) {
            if (tid < o * 16) { r1[tid] += r1[tid + o * 16]; r2[tid] += r2[tid + o * 16]; }
            __syncthreads();
        }
        if (tid < 16) { part[64 + tid] = r1[tid]; partq[64 + tid] = r2[tid]; }
    }
}

// ============================================================
// K2: FUSED front, all fp16: enc -> sel -> kv (BN reduction inlined)
// ============================================================
constexpr int FR_OFF_AE   = 0;                            // 10240
constexpr int FR_OFF_A16  = 10240;                        // 16384
constexpr int FR_OFF_W    = 26624;                        // 73728
constexpr int FR_OFF_MISC = 100352;                       // 544 floats
constexpr int SMEM_FRONT  = 102528;

__global__ void __launch_bounds__(256, 2)
k_front(const float* __restrict__ s, const float* __restrict__ a,
        const float* __restrict__ Bsa, const float* __restrict__ Bse,
        const float* __restrict__ bv)
{
    extern __shared__ char smc[];
    uint32_t* uAe  = (uint32_t*)(smc + FR_OFF_AE);
    uint32_t* uA16 = (uint32_t*)(smc + FR_OFF_A16);
    uint2*    W    = (uint2*)(smc + FR_OFF_W);
    char*     Wc   = smc + FR_OFF_W;
    float*   bsa = (float*)(smc + FR_OFF_MISC);
    float*   bse = bsa + 128;
    float*   bvv = bse + 128;
    float*   mn  = bvv + 128;
    float*   rsd = mn + 80;

    const int n = blockIdx.y, tid = threadIdx.x;
    const size_t gr0 = (size_t)n * B + (size_t)blockIdx.x * 64;

    for (int c = tid; c < 2304; c += 256) {
        const char* src = (c < 1280) ? (const char*)pWsa16[n] + c * 16
                                     : (const char*)pWse16[n] + (c - 1280) * 16;
        cp16(Wc + c * 16, src);
    }
    CP_COMMIT();

    for (int i = tid; i < 128; i += 256) {
        bsa[i] = Bsa[n * HID + i];
        bse[i] = Bse[n * HID + i];
        bvv[i] = bv[i];
    }
    for (int i = tid; i < 80; i += 256) {
        float sum = 0.f, sq = 0.f;
        #pragma unroll
        for (int c = 0; c < 16; c++) {
            sum += g_part [(n * 16 + c) * KSA + i];
            sq  += g_partq[(n * 16 + c) * KSA + i];
        }
        float m = sum * (1.f / B);
        mn[i]  = m;
        rsd[i] = rsqrtf(sq * (1.f / B) - m * m + EPS);
    }
    __syncthreads();

    for (int i = tid; i < 64 * 20; i += 256) {
        int r = i / 20, c4 = i - r * 20;
        size_t row = gr0 + r;
        float4 v = (c4 < 16) ? ((const float4*)s)[row * 16 + c4]
                             : ((const float4*)a)[row * 4 + (c4 - 16)];
        int C = c4 * 4;
        float f0 = (v.x - mn[C])     * rsd[C];
        float f1 = (v.y - mn[C + 1]) * rsd[C + 1];
        float f2 = (v.z - mn[C + 2]) * rsd[C + 2];
        float f3 = (v.w - mn[C + 3]) * rsd[C + 3];
        int ksh = C >> 4, co = C & 15;
        int g16 = r >> 4, rr = r & 15;
        int comp = (rr >> 3) & 1, gp = rr & 7;
        int tig0 = (co & 7) >> 1;
        uint32_t* base = uAe + (((g16 * 5 + ksh) << 5) + (gp << 2) + tig0) * 4
                         + ((co >= 8) ? 2 : 0) + comp;
        base[0] = h2(f0, f1);
        base[4] = h2(f2, f3);
    }
    CP_WAITG(0);
    __syncthreads();

    const int w = tid >> 5, lane = tid & 31;
    const int rs_ = w & 1, t0 = w >> 1;
    const int g = lane >> 2, tig = lane & 3;

    // ---- Phase 1: enc ----
    float4 ae[2][4], as_[2][4];
    #pragma unroll
    for (int mi = 0; mi < 2; mi++)
        #pragma unroll
        for (int j = 0; j < 4; j++) { ae[mi][j] = make_float4(0,0,0,0); as_[mi][j] = make_float4(0,0,0,0); }

    #pragma unroll
    for (int ksh = 0; ksh < 5; ksh++) {
        uint4 fa0 = *(const uint4*)(uAe + (((rs_*2)   * 5 + ksh) << 7) + (lane << 2));
        uint4 fa1 = *(const uint4*)(uAe + (((rs_*2+1) * 5 + ksh) << 7) + (lane << 2));
        #pragma unroll
        for (int j = 0; j < 4; j++) {
            uint2 bb = W[((t0 * 4 + j) * 5 + ksh) * 32 + lane];
            mma16(ae[0][j], fa0, bb); mma16(ae[1][j], fa1, bb);
        }
        if (ksh < 4) {
            #pragma unroll
            for (int j = 0; j < 4; j++) {
                uint2 bb = W[2560 + ((t0 * 4 + j) * 4 + ksh) * 32 + lane];
                mma16(as_[0][j], fa0, bb); mma16(as_[1][j], fa1, bb);
            }
        }
    }
    __syncthreads();

    for (int c = tid; c < 2048; c += 256) cp16(Wc + c * 16, (const char*)pWsel16 + c * 16);
    CP_COMMIT();

    uint32_t* gseT = (uint32_t*)g_se + ((gr0 >> 6) << 12);
    #pragma unroll
    for (int mi = 0; mi < 2; mi++) {
        #pragma unroll
        for (int j = 0; j < 4; j++) {
            int c = t0 * 32 + j * 8 + 2 * tig;
            float b0e = bsa[c], b1e = bsa[c + 1];
            float b0s = bse[c], b1s = bse[c + 1];
            ae[mi][j]  = make_float4(lrelu(ae[mi][j].x + b0e), lrelu(ae[mi][j].y + b1e),
                                     lrelu(ae[mi][j].z + b0e), lrelu(ae[mi][j].w + b1e));
            as_[mi][j] = make_float4(lrelu(as_[mi][j].x + b0s), lrelu(as_[mi][j].y + b1s),
                                     lrelu(as_[mi][j].z + b0s), lrelu(as_[mi][j].w + b1s));
            st_frag16(uA16, rs_ * 2 + mi, t0 * 4 + j, tig, g, as_[mi][j]);
            st_frag16(gseT, rs_ * 2 + mi, t0 * 4 + j, tig, g, as_[mi][j]);
        }
    }
    CP_WAITG(0);
    __syncthreads();

    // ---- Phase 2: sel ----
    float4 ac[2][4], acv[2][4];
    #pragma unroll
    for (int mi = 0; mi < 2; mi++)
        #pragma unroll
        for (int j = 0; j < 4; j++) ac[mi][j] = make_float4(0,0,0,0);

    #pragma unroll
    for (int ksh = 0; ksh < 8; ksh++) {
        uint4 fa0 = ldfrag16(uA16, rs_ * 2,     ksh, lane);
        uint4 fa1 = ldfrag16(uA16, rs_ * 2 + 1, ksh, lane);
        #pragma unroll
        for (int j = 0; j < 4; j++) {
            uint2 bb = W[((t0 * 4 + j) * 8 + ksh) * 32 + lane];
            mma16(ac[0][j], fa0, bb); mma16(ac[1][j], fa1, bb);
        }
    }
    __syncthreads();

    for (int c = tid; c < 4096; c += 256) {
        const char* src = (c < 2048) ? (const char*)pWk16 + c * 16
                                     : (const char*)pWv16 + (c - 2048) * 16;
        cp16(Wc + c * 16, src);
    }
    CP_COMMIT();

    #pragma unroll
    for (int mi = 0; mi < 2; mi++) {
        #pragma unroll
        for (int j = 0; j < 4; j++) {
            int c = t0 * 32 + j * 8 + 2 * tig;
            size_t gr = gr0 + rs_ * 32 + mi * 16 + g;
            *(uint32_t*)&g_sel[gr * 128 + c]       = h2(ac[mi][j].x, ac[mi][j].y);
            *(uint32_t*)&g_sel[(gr + 8) * 128 + c] = h2(ac[mi][j].z, ac[mi][j].w);
            st_frag16(uA16, rs_ * 2 + mi, t0 * 4 + j, tig, g, ae[mi][j]);
        }
    }
    CP_WAITG(0);
    __syncthreads();

    // ---- Phase 3: key + val ----
    #pragma unroll
    for (int mi = 0; mi < 2; mi++)
        #pragma unroll
        for (int j = 0; j < 4; j++) { ac[mi][j] = make_float4(0,0,0,0); acv[mi][j] = make_float4(0,0,0,0); }

    #pragma unroll
    for (int ksh = 0; ksh < 8; ksh++) {
        uint4 fa0 = ldfrag16(uA16, rs_ * 2,     ksh, lane);
        uint4 fa1 = ldfrag16(uA16, rs_ * 2 + 1, ksh, lane);
        #pragma unroll
        for (int j = 0; j < 4; j++) {
            int bi = ((t0 * 4 + j) * 8 + ksh) * 32 + lane;
            uint2 bk = W[bi], bw = W[4096 + bi];
            mma16(ac[0][j],  fa0, bk); mma16(ac[1][j],  fa1, bk);
            mma16(acv[0][j], fa0, bw); mma16(acv[1][j], fa1, bw);
        }
    }

    #pragma unroll
    for (int mi = 0; mi < 2; mi++) {
        #pragma unroll
        for (int j = 0; j < 4; j++) {
            size_t gr = gr0 + rs_ * 32 + mi * 16 + g;
            int c = t0 * 32 + j * 8 + 2 * tig;
            *(uint32_t*)&g_key[gr * 128 + c]       = h2(ac[mi][j].x, ac[mi][j].y);
            *(uint32_t*)&g_key[(gr + 8) * 128 + c] = h2(ac[mi][j].z, ac[mi][j].w);
            float bb0 = bvv[c], bb1 = bvv[c + 1];
            *(uint32_t*)&g_val[gr * 128 + c]       = h2(lrelu(acv[mi][j].x + bb0), lrelu(acv[mi][j].y + bb1));
            *(uint32_t*)&g_val[(gr + 8) * 128 + c] = h2(lrelu(acv[mi][j].z + bb0), lrelu(acv[mi][j].w + bb1));
        }
    }
}

// ============================================================
// K3: attention — vectorized smem (float4 LDS/STS, register AV)
// ============================================================
constexpr int ASTR = 36;
__global__ void __launch_bounds__(256, 4)
k_attn()
{
    __shared__ float smem[8][3 * 8 * ASTR + 64];
    const int tid = threadIdx.x, warp = tid >> 5, lane = tid & 31;
    const int gid = blockIdx.x * 8 + warp;
    const int b = gid >> 2;
    const int p = gid & 3;

    float* selS = smem[warp];
    float* keyS = selS + 8 * ASTR;
    float* valS = keyS + 8 * ASTR;
    float* wS   = valS + 8 * ASTR;
    const float scale = 0.17677669529663687f;

    #pragma unroll
    for (int it = 0; it < 3; it++) {
        int idx = it * 32 + lane;
        int seg = idx >> 2, q4 = idx & 3;
        int arr = seg >> 3, i = seg & 7;
        const __half* gsrc = (arr == 0) ? g_sel : (arr == 1) ? g_key : g_val;
        uint4 v = *(const uint4*)(gsrc + ((size_t)i * B + b) * HID + p * D + q4 * 8);
        const __half2* hp = (const __half2*)&v;
        float2 f0 = __half22float2(hp[0]);
        float2 f1 = __half22float2(hp[1]);
        float2 f2 = __half22float2(hp[2]);
        float2 f3 = __half22float2(hp[3]);
        float* dst = selS + arr * (8 * ASTR) + i * ASTR + q4 * 8;
        *(float4*)dst       = make_float4(f0.x, f0.y, f1.x, f1.y);
        *(float4*)(dst + 4) = make_float4(f2.x, f2.y, f3.x, f3.y);
    }
    __syncwarp();

    const int i0 = lane >> 3, j = lane & 7;
    const float4* selR0 = (const float4*)(selS + i0 * ASTR);
    const float4* selR1 = (const float4*)(selS + (i0 + 4) * ASTR);
    const float4* keyR  = (const float4*)(keyS + j * ASTR);
    float acc0 = 0.f, acc1 = 0.f;
    #pragma unroll
    for (int d4 = 0; d4 < 8; d4++) {
        float4 kv = keyR[d4];
        float4 sa = selR0[d4], sb = selR1[d4];
        acc0 += sa.x * kv.x + sa.y * kv.y + sa.z * kv.z + sa.w * kv.w;
        acc1 += sb.x * kv.x + sb.y * kv.y + sb.z * kv.z + sb.w * kv.w;
    }
    acc0 *= scale; acc1 *= scale;
    if (i0 == j)     acc0 = -1e9f;
    if (i0 + 4 == j) acc1 = -1e9f;

    float m0 = acc0, m1 = acc1;
    #pragma unroll
    for (int o = 1; o < 8; o <<= 1) {
        m0 = fmaxf(m0, __shfl_xor_sync(FULLMASK, m0, o));
        m1 = fmaxf(m1, __shfl_xor_sync(FULLMASK, m1, o));
    }
    float e0 = __expf(acc0 - m0), e1 = __expf(acc1 - m1);
    float s0 = e0, s1 = e1;
    #pragma unroll
    for (int o = 1; o < 8; o <<= 1) {
        s0 += __shfl_xor_sync(FULLMASK, s0, o);
        s1 += __shfl_xor_sync(FULLMASK, s1, o);
    }
    wS[lane]      = __fdividef(e0, s0);
    wS[lane + 32] = __fdividef(e1, s1);
    __syncwarp();

    float v[8];
    #pragma unroll
    for (int jj = 0; jj < 8; jj++) v[jj] = valS[jj * ASTR + lane];
    #pragma unroll
    for (int ii = 0; ii < 8; ii++) {
        float4 wa = *(const float4*)(wS + ii * 8);
        float4 wb = *(const float4*)(wS + ii * 8 + 4);
        float o = wa.x * v[0] + wa.y * v[1] + wa.z * v[2] + wa.w * v[3]
                + wb.x * v[4] + wb.y * v[5] + wb.z * v[6] + wb.w * v[7];
        g_oth[((size_t)ii * B + b) * HID + p * D + lane] = __float2half_rn(o);
    }
}

// ============================================================
// K4: critic fp16 — 32-row tiles, 128 threads, 3 blocks/SM,
// single-buffer W1 (re-stage hidden across co-resident blocks);
// selected-column layer 2
// ============================================================
constexpr int HSTR   = 132;   // f32 h stride
constexpr int OSTRU  = 68;    // oth A row stride in u32 (136 halves)
constexpr int CR_OFF_A   = 0;                             // 16896: se frag [0,8192) + oth [8192,16896)
constexpr int CR_OFF_B1  = 16896;                         // 32768 (single buffer)
constexpr int CR_OFF_W2  = 49664;                         // 8448
constexpr int CR_OFF_B1S = 58112;                         // 512
constexpr int CR_OFF_B2S = 58624;                         // 64
constexpr int CR_OFF_AMX = 58688;                         // 128
constexpr int SMEM_CRIT  = 58816;

__device__ __forceinline__ void crit_stageW16(uint2* B1, int ph, int n, int tid) {
    const uint2* base = pWc116[n];
    for (int cc = tid; cc < 2048; cc += 128) {
        int lanepair = cc & 15, ksl = (cc >> 4) & 7, n8 = cc >> 7;
        cp16(B1 + (n8 * 8 + ksl) * 32 + lanepair * 2,
             base + ((n8 * 16 + ph * 8 + ksl) * 32 + lanepair * 2));
    }
}

__global__ void __launch_bounds__(128, 3)
k_crit(const float* __restrict__ a,
       const float* __restrict__ Bc1,
       const float* __restrict__ Wc2, const float* __restrict__ Bc2,
       float* __restrict__ out)
{
    extern __shared__ char smc[];
    uint32_t* uA  = (uint32_t*)(smc + CR_OFF_A);      // se frag half-tile (2048 u32)
    uint32_t* uAo = uA + 2048;                        // oth rows (32 x OSTRU)
    uint2*    B1  = (uint2*)(smc + CR_OFF_B1);
    float*    h   = (float*)(smc + CR_OFF_A);         // reuses A region (32*132*4 = 16896)
    float*   w2t  = (float*)(smc + CR_OFF_W2);
    float*   b1s  = (float*)(smc + CR_OFF_B1S);
    float*   b2s  = (float*)(smc + CR_OFF_B2S);
    int*     amx  = (int*)(smc + CR_OFF_AMX);

    const int n = blockIdx.y, tid = threadIdx.x;
    const int w = tid >> 5, lane = tid & 31;
    const size_t row0 = (size_t)n * B + (size_t)blockIdx.x * 32;

    // group 1: W1 ph0 + A_se (half of 64-row fragment tile: g16 pair)
    crit_stageW16(B1, 0, n, tid);
    {
        const uint32_t* gseT = (const uint32_t*)g_se + ((row0 >> 6) << 12)
                               + (((row0 >> 5) & 1) << 11);   // half offset: 2048 u32
        for (int i = tid; i < 512; i += 128) cp16(uA + i * 4, gseT + i * 4);
    }
    CP_COMMIT();
    // group 2: A_oth
    for (int i = tid; i < 512; i += 128) {
        int r = i >> 4, c = i & 15;
        cp16(uAo + r * OSTRU + c * 4,
             (const uint32_t*)g_oth + (row0 + r) * 64 + c * 4);
    }
    CP_COMMIT();

    // small fills overlap async copies
    for (int i = tid; i < HID * AD; i += 128) {
        int k = i >> 4, o = i & 15;
        w2t[o * HSTR + k] = Wc2[n * HID * AD + k * AD + o];
    }
    b1s[tid] = Bc1[n * HID + tid];
    if (tid < AD) b2s[tid] = Bc2[n * AD + tid];
    if (tid < 32) {
        const float4* ap = (const float4*)(a + (row0 + tid) * AD);
        float4 q0 = ap[0], q1 = ap[1], q2 = ap[2], q3 = ap[3];
        float vals[16] = {q0.x,q0.y,q0.z,q0.w, q1.x,q1.y,q1.z,q1.w,
                          q2.x,q2.y,q2.z,q2.w, q3.x,q3.y,q3.z,q3.w};
        int bi = 0; float bvv = vals[0];
        #pragma unroll
        for (int i = 1; i < 16; i++) if (vals[i] > bvv) { bvv = vals[i]; bi = i; }
        amx[tid] = bi;
    }

    const int cq = w;                    // 4 warps = 4 col quarters
    const int g = lane >> 2, tig = lane & 3;

    float4 acc[2][4];
    #pragma unroll
    for (int mi = 0; mi < 2; mi++)
        #pragma unroll
        for (int j = 0; j < 4; j++) acc[mi][j] = make_float4(0,0,0,0);

    CP_WAITG(1);            // group 1 done (group 2 may be pending)
    __syncthreads();

    // ---- ph0: se (fragment-order fp16, g16 0..1 = rows 0..31) ----
    #pragma unroll
    for (int ksl = 0; ksl < 8; ksl++) {
        uint4 fa0 = ldfrag16(uA, 0, ksl, lane);
        uint4 fa1 = ldfrag16(uA, 1, ksl, lane);
        #pragma unroll
        for (int j = 0; j < 4; j++) {
            uint2 bb = B1[((cq * 4 + j) * 8 + ksl) * 32 + lane];
            mma16(acc[0][j], fa0, bb); mma16(acc[1][j], fa1, bb);
        }
    }
    __syncthreads();        // everyone done reading B1 before re-stage

    // group 3: W1 ph1 into same buffer (exposure hidden by co-resident blocks)
    crit_stageW16(B1, 1, n, tid);
    CP_COMMIT();
    CP_WAITG(0);            // groups 2 + 3 done
    __syncthreads();

    // ---- ph1: oth (row-major fp16, rows 0..31) ----
    #pragma unroll
    for (int ksl = 0; ksl < 8; ksl++) {
        uint4 fa0, fa1;
        {
            const uint32_t* b0 = uAo + g * OSTRU + ksl * 8 + tig;
            fa0 = make_uint4(b0[0], b0[8 * OSTRU], b0[4], b0[8 * OSTRU + 4]);
            const uint32_t* b1 = b0 + 16 * OSTRU;
            fa1 = make_uint4(b1[0], b1[8 * OSTRU], b1[4], b1[8 * OSTRU + 4]);
        }
        #pragma unroll
        for (int j = 0; j < 4; j++) {
            uint2 bb = B1[((cq * 4 + j) * 8 + ksl) * 32 + lane];
            mma16(acc[0][j], fa0, bb); mma16(acc[1][j], fa1, bb);
        }
    }
    __syncthreads();        // all A reads done before h overwrites uA

    #pragma unroll
    for (int mi = 0; mi < 2; mi++) {
        #pragma unroll
        for (int j = 0; j < 4; j++) {
            int r = mi * 16 + g;
            int c = cq * 32 + j * 8 + 2 * tig;
            float bb0 = b1s[c], bb1 = b1s[c + 1];
            *(float2*)&h[r * HSTR + c]       = make_float2(lrelu(acc[mi][j].x + bb0), lrelu(acc[mi][j].y + bb1));
            *(float2*)&h[(r + 8) * HSTR + c] = make_float2(lrelu(acc[mi][j].z + bb0), lrelu(acc[mi][j].w + bb1));
        }
    }
    __syncthreads();

    // layer 2: only the selected output column per row (warp w: rows w*8..w*8+7)
    #pragma unroll
    for (int rr = 0; rr < 8; rr++) {
        const int r = w * 8 + rr;
        const int o = amx[r];
        float4 hv = *(const float4*)(h + r * HSTR + lane * 4);
        float4 wv = *(const float4*)(w2t + o * HSTR + lane * 4);
        float q = hv.x * wv.x + hv.y * wv.y + hv.z * wv.z + hv.w * wv.w;
        #pragma unroll
        for (int off = 16; off > 0; off >>= 1)
            q += __shfl_xor_sync(FULLMASK, q, off);
        if (lane == 0)
            out[(size_t)n * B + blockIdx.x * 32 + r] = q + b2s[o];
    }
}

// ============================================================
extern "C" void kernel_launch(void* const* d_in, const int* in_sizes, int n_in,
                              void* d_out, int out_size)
{
    const float* s    = (const float*)d_in[0];
    const float* a    = (const float*)d_in[1];
    const float* Wsa  = (const float*)d_in[2];
    const float* Bsa  = (const float*)d_in[3];
    const float* Wse  = (const float*)d_in[4];
    const float* Bse  = (const float*)d_in[5];
    const float* Wk   = (const float*)d_in[6];
    const float* Wsel = (const float*)d_in[7];
    const float* Wv   = (const float*)d_in[8];
    const float* bv   = (const float*)d_in[9];
    const float* Wc1  = (const float*)d_in[10];
    const float* Bc1  = (const float*)d_in[11];
    const float* Wc2  = (const float*)d_in[12];
    const float* Bc2  = (const float*)d_in[13];
    float* out = (float*)d_out;

    cudaFuncSetAttribute(k_front, cudaFuncAttributeMaxDynamicSharedMemorySize, SMEM_FRONT);
    cudaFuncSetAttribute(k_crit,  cudaFuncAttributeMaxDynamicSharedMemorySize, SMEM_CRIT);

    k_prep_stats<<<352, 512>>>(Wk, Wv, Wsel, Wsa, Wse, Wc1, s, a);
    k_front     <<<dim3(B / 64, NAG), 256, SMEM_FRONT>>>(s, a, Bsa, Bse, bv);
    k_attn      <<<dim3((HEADS * B) / 8), 256>>>();
    k_crit      <<<dim3(B / 32, NAG), 128, SMEM_CRIT>>>(a, Bc1, Wc2, Bc2, out);
}